// round 6
// baseline (speedup 1.0000x reference)
#include <cuda_runtime.h>
#include <math.h>

#define NS     64
#define HID    20
#define HDIM   1280
#define BATCH  16384
#define MROWS  8
#define T      768
#define NJP    96              // target-pair lanes (T/8)
#define PSTR   1284            // even => b64-aligned pair targets
#define P6STR  68
#define LVL    806400          // 2016*400 floats per level

typedef unsigned long long ull;

// fc2..fc5 scatter weights, target-pair/ci-pair chunk-major:
//   slab si (npairs=(63-si)*10): float4 at [kk*npairs + jp] =
//   (W[j0][ci0], W[j1][ci0], W[j0][ci1], W[j1][ci1]), j0=2jp, j1=2jp+1, ci0=2kk, ci1=2kk+1
__device__ float g_Ws4[4 * LVL];
__device__ float g_W1s[2016 * 20];      // fc1 scalar, j-major (natural pairs)
__device__ float g_W6s[2016 * 20];      // fc6 target-major [t*20 + ci]
__device__ float g_Wd [64 * 2020];      // diag per si: [lv*400 + ci*20 + c], fc6 at 2000

__device__ __forceinline__ int slab_off1(int si) { return 63 * si - (si * (si - 1)) / 2; }

__global__ void prep_scatter(const float* __restrict__ W1, const float* __restrict__ W2,
                             const float* __restrict__ W3, const float* __restrict__ W4,
                             const float* __restrict__ W5, const float* __restrict__ W6)
{
    const int si = blockIdx.x, what = blockIdx.y;
    const int nso1 = 63 - si;
    const int nt = nso1 * 20;
    if (what < 4) {
        const float* W = (what == 0) ? W2 : (what == 1) ? W3 : (what == 2) ? W4 : W5;
        float* dst = g_Ws4 + (size_t)what * LVL + (size_t)slab_off1(si) * 400;
        const int npairs = nso1 * 10;
        const int cnt = nso1 * 400;
        for (int t = threadIdx.x; t < cnt; t += blockDim.x) {
            int m = t & 3, f = t >> 2;
            int jp = f % npairs, kk = f / npairs;
            int j = 2 * jp + (m & 1);
            int so = si + 1 + j / 20, c = j % 20, ci = 2 * kk + (m >> 1);
            dst[t] = W[(size_t)(c * NS + so) * HDIM + ci * NS + si];
        }
    } else if (what == 4) {
        float* d1 = g_W1s + (size_t)slab_off1(si) * 20;
        for (int t = threadIdx.x; t < nt; t += blockDim.x) {
            int so = si + 1 + t / 20, c = t % 20;
            d1[t] = W1[(size_t)(c * NS + so) * NS + si];
        }
        float* dd = g_Wd + (size_t)si * 2020;
        for (int t = threadIdx.x; t < 2020; t += blockDim.x) {
            if (t < 1600) {
                int lv = t / 400, rem = t - lv * 400;
                int ci = rem / 20, c = rem - ci * 20;
                const float* W = (lv == 0) ? W2 : (lv == 1) ? W3 : (lv == 2) ? W4 : W5;
                dd[t] = W[(size_t)(c * NS + si) * HDIM + ci * NS + si];
            } else if (t < 2000) {
                dd[t] = 0.0f;
            } else {
                dd[t] = W6[(size_t)si * HDIM + (t - 2000) * NS + si];
            }
        }
    } else {
        float* d6 = g_W6s + (size_t)slab_off1(si) * 20;
        for (int t = threadIdx.x; t < nt; t += blockDim.x) {
            int tt = t / 20, ci = t - tt * 20;
            int so = si + 1 + tt;
            d6[t] = W6[(size_t)so * HDIM + ci * NS + si];
        }
    }
}

__device__ __forceinline__ ull ffma2(ull a, ull b, ull c)
{
    ull d;
    asm("fma.rn.f32x2 %0, %1, %2, %3;" : "=l"(d) : "l"(a), "l"(b), "l"(c));
    return d;
}
__device__ __forceinline__ ull fadd2(ull a, ull b)
{
    ull d;
    asm("add.rn.f32x2 %0, %1, %2;" : "=l"(d) : "l"(a), "l"(b));
    return d;
}
__device__ __forceinline__ ull pack2(float lo, float hi)
{
    ull v;
    asm("mov.b64 %0, {%1, %2};" : "=l"(v) : "f"(lo), "f"(hi));
    return v;
}
__device__ __forceinline__ float sigmoidf(float x) { return 1.0f / (1.0f + expf(-x)); }

#define BAR_DIAG() asm volatile("bar.sync 1, 160;" ::: "memory")

__global__ void __launch_bounds__(T, 1)
net_kernel(const float* __restrict__ u, float* __restrict__ out)
{
    extern __shared__ float sm[];
    ull*   hdu  = (ull*)sm;                 // [5][8][20] dup-packed h (ull each)
    float* pre  = sm + 1600;                // [5][8][PSTR]
    float* pre6 = pre + 5 * MROWS * PSTR;   // [8][P6STR]
    float* usm  = pre6 + MROWS * P6STR;     // [8][64]
    float* wd   = usm + 512;                // [2020]
    ull*   svd  = (ull*)(wd + 2020);        // [8] dup-packed sample

    const int tid = threadIdx.x;
    const int r   = tid & 7;
    const int jpl = tid >> 3;               // 0..95 target-pair lane

    for (int k = tid; k < 5 * MROWS * PSTR; k += T) pre[k] = 0.0f;
    for (int k = tid; k < MROWS * P6STR; k += T) pre6[k] = 0.0f;
    if (tid < 512) {
        int ii = tid >> 3, rr = tid & 7;
        usm[rr * NS + ii] = u[(size_t)ii * BATCH + (size_t)blockIdx.x * MROWS + rr];
    }
    for (int k = tid; k < 2020; k += T) wd[k] = g_Wd[k];
    __syncthreads();

    for (int i = 0; i < NS; ++i) {
        // ===== diagonal chain: 160 threads, named barriers =====
        if (tid < 160) {
            const int dr = tid / 20, dc = tid - (tid / 20) * 20;
            const float* hlo = (const float*)hdu;      // dup array, lo half = scalar h
            {
                float v = sigmoidf(pre[dr * PSTR + i * HID + dc]);
                hdu[dr * 20 + dc] = pack2(v, v);
            }
            BAR_DIAG();
            #pragma unroll 1
            for (int lv = 0; lv < 4; ++lv) {
                float acc = pre[((lv + 1) * MROWS + dr) * PSTR + i * HID + dc];
                const float* w  = wd + lv * 400 + dc;             // [ci*20 + c]
                const float* hh = hlo + (lv * 160 + dr * 20) * 2; // lo halves, stride 2
                #pragma unroll
                for (int ci = 0; ci < 20; ++ci) acc = fmaf(w[ci * 20], hh[2 * ci], acc);
                float v = sigmoidf(acc);
                hdu[(lv + 1) * 160 + dr * 20 + dc] = pack2(v, v);
                BAR_DIAG();
            }
            if (tid < MROWS) {                                    // fc6 diag + sample
                float acc = pre6[tid * P6STR + i];
                const float* hh = hlo + (4 * 160 + tid * 20) * 2;
                #pragma unroll
                for (int ci = 0; ci < 20; ++ci) acc = fmaf(wd[2000 + ci], hh[2 * ci], acc);
                float x = sigmoidf(acc);
                out[((size_t)blockIdx.x * MROWS + tid) * NS + i] = x;
                float s = (x >= usm[tid * NS + i]) ? 1.0f : -1.0f;
                svd[tid] = pack2(s, s);
            }
        }
        __syncthreads();

        // ===== scatter phase =====
        if (i < 63) {
            const int nso1 = 63 - i;
            const int npairs = nso1 * 10;
            const int tbase = (i + 1) * HID;          // even
            const size_t soff = (size_t)slab_off1(i);

            // fc2..fc5: thread (r, jpl) RMWs pre[l+1][r] pair (j0,j1) as b64
            #pragma unroll 1
            for (int l = 0; l < 4; ++l) {
                const ulonglong2* wb = (const ulonglong2*)(g_Ws4 + (size_t)l * LVL + soff * 400);
                ull* prl = (ull*)(pre + (size_t)(l + 1) * MROWS * PSTR + r * PSTR + tbase);
                // hoist dup-packed h (40 regs)
                ull hd[20];
                {
                    const ulonglong2* hp = (const ulonglong2*)(hdu + (l * MROWS + r) * 20);
                    #pragma unroll
                    for (int q = 0; q < 10; ++q) { ulonglong2 a = hp[q]; hd[2*q] = a.x; hd[2*q+1] = a.y; }
                }
                #pragma unroll 1
                for (int jp = jpl; jp < npairs; jp += NJP) {
                    const ulonglong2* wp = wb + jp;
                    ull* dp = prl + jp;
                    ull a0 = *dp;
                    ull a1 = pack2(0.0f, 0.0f);
                    // half 1: kk 0..4 (5 LDG.128)
                    {
                        ulonglong2 w0 = wp[0*npairs], w1 = wp[1*npairs], w2 = wp[2*npairs],
                                   w3 = wp[3*npairs], w4 = wp[4*npairs];
                        a0 = ffma2(w0.x, hd[0], a0); a1 = ffma2(w0.y, hd[1], a1);
                        a0 = ffma2(w1.x, hd[2], a0); a1 = ffma2(w1.y, hd[3], a1);
                        a0 = ffma2(w2.x, hd[4], a0); a1 = ffma2(w2.y, hd[5], a1);
                        a0 = ffma2(w3.x, hd[6], a0); a1 = ffma2(w3.y, hd[7], a1);
                        a0 = ffma2(w4.x, hd[8], a0); a1 = ffma2(w4.y, hd[9], a1);
                    }
                    // half 2: kk 5..9
                    {
                        ulonglong2 w5 = wp[5*npairs], w6 = wp[6*npairs], w7 = wp[7*npairs],
                                   w8 = wp[8*npairs], w9 = wp[9*npairs];
                        a0 = ffma2(w5.x, hd[10], a0); a1 = ffma2(w5.y, hd[11], a1);
                        a0 = ffma2(w6.x, hd[12], a0); a1 = ffma2(w6.y, hd[13], a1);
                        a0 = ffma2(w7.x, hd[14], a0); a1 = ffma2(w7.y, hd[15], a1);
                        a0 = ffma2(w8.x, hd[16], a0); a1 = ffma2(w8.y, hd[17], a1);
                        a0 = ffma2(w9.x, hd[18], a0); a1 = ffma2(w9.y, hd[19], a1);
                    }
                    *dp = fadd2(a0, a1);
                }
            }
            // fc1 rank-1, b64 pairs
            {
                const float* wb1 = g_W1s + soff * 20;
                ull* p1 = (ull*)(pre + r * PSTR + tbase);
                const ull s2 = svd[r];
                #pragma unroll 1
                for (int jp = jpl; jp < npairs; jp += NJP) {
                    ull w2 = *(const ull*)(wb1 + 2 * jp);
                    p1[jp] = ffma2(w2, s2, p1[jp]);
                }
            }
            // fc6: scalar, one target per (r, jpl<nso1) — once per step
            if (jpl < nso1) {
                const float* wb6 = g_W6s + soff * 20 + (size_t)jpl * 20;
                const float* hh = (const float*)(hdu + (4 * MROWS + r) * 20);  // lo halves
                float acc = pre6[r * P6STR + (i + 1 + jpl)];
                #pragma unroll
                for (int ci = 0; ci < 20; ++ci) acc = fmaf(wb6[ci], hh[2 * ci], acc);
                pre6[r * P6STR + (i + 1 + jpl)] = acc;
            }
            // prefetch next step's diag weights
            {
                const float* src = g_Wd + (size_t)(i + 1) * 2020;
                for (int k = tid; k < 2020; k += T) wd[k] = src[k];
            }
        }
        __syncthreads();
    }
}

extern "C" void kernel_launch(void* const* d_in, const int* in_sizes, int n_in,
                              void* d_out, int out_size)
{
    (void)in_sizes; (void)n_in; (void)out_size;
    const float* u  = (const float*)d_in[1];
    const float* W1 = (const float*)d_in[2];
    const float* W2 = (const float*)d_in[3];
    const float* W3 = (const float*)d_in[4];
    const float* W4 = (const float*)d_in[5];
    const float* W5 = (const float*)d_in[6];
    const float* W6 = (const float*)d_in[7];
    float* out = (float*)d_out;

    dim3 pg(64, 6);
    prep_scatter<<<pg, 256>>>(W1, W2, W3, W4, W5, W6);

    const int smem_bytes = (1600 + 5 * MROWS * PSTR + MROWS * P6STR
                            + 512 + 2020 + 16) * (int)sizeof(float);   // 224,272 B
    cudaFuncSetAttribute(net_kernel, cudaFuncAttributeMaxDynamicSharedMemorySize, smem_bytes);
    net_kernel<<<BATCH / MROWS, T, smem_bytes>>>(u, out);
}

// round 7
// speedup vs baseline: 1.8065x; 1.8065x over previous
#include <cuda_runtime.h>
#include <math.h>

#define NS     64
#define HID    20
#define HDIM   1280
#define BATCH  16384
#define MROWS  8
#define T      512
#define NJJ    128             // target lanes (T/4)
#define PSTR   1284
#define P6STR  68
#define LVL    806400          // 2016*400 floats per level

typedef unsigned long long ull;

// Chunk-major scatter weights (R3 layout — best measured):
//   slab si (nt=(63-si)*20 targets): float4 at [k*nt + j] = W[j][4k..4k+3]
__device__ float g_Ws4[4 * LVL];
__device__ float g_W1s[2016 * 20];      // fc1 scalar, j-major
__device__ float g_W6s[2016 * 20];      // fc6 chunk-major: (k, t) float4
__device__ float g_Wd [64 * 2020];      // diag per si: [lv*400 + ci*20 + c], fc6 at 2000

__device__ __forceinline__ int slab_off1(int si) { return 63 * si - (si * (si - 1)) / 2; }

__global__ void prep_scatter(const float* __restrict__ W1, const float* __restrict__ W2,
                             const float* __restrict__ W3, const float* __restrict__ W4,
                             const float* __restrict__ W5, const float* __restrict__ W6)
{
    const int si = blockIdx.x, what = blockIdx.y;
    const int nso1 = 63 - si;
    const int nt = nso1 * 20;
    if (what < 4) {
        const float* W = (what == 0) ? W2 : (what == 1) ? W3 : (what == 2) ? W4 : W5;
        float* dst = g_Ws4 + (size_t)what * LVL + (size_t)slab_off1(si) * 400;
        const int cnt = nso1 * 400;
        for (int t = threadIdx.x; t < cnt; t += blockDim.x) {
            int m = t & 3, q = t >> 2;
            int j = q % nt, k = q / nt;
            int so = si + 1 + j / 20, c = j % 20, ci = 4 * k + m;
            dst[t] = W[(size_t)(c * NS + so) * HDIM + ci * NS + si];
        }
    } else if (what == 4) {
        float* d1 = g_W1s + (size_t)slab_off1(si) * 20;
        for (int t = threadIdx.x; t < nt; t += blockDim.x) {
            int so = si + 1 + t / 20, c = t % 20;
            d1[t] = W1[(size_t)(c * NS + so) * NS + si];
        }
        float* dd = g_Wd + (size_t)si * 2020;
        for (int t = threadIdx.x; t < 2020; t += blockDim.x) {
            if (t < 1600) {
                int lv = t / 400, rem = t - lv * 400;
                int ci = rem / 20, c = rem - ci * 20;
                const float* W = (lv == 0) ? W2 : (lv == 1) ? W3 : (lv == 2) ? W4 : W5;
                dd[t] = W[(size_t)(c * NS + si) * HDIM + ci * NS + si];
            } else if (t < 2000) {
                dd[t] = 0.0f;
            } else {
                dd[t] = W6[(size_t)si * HDIM + (t - 2000) * NS + si];
            }
        }
    } else {
        float* d6 = g_W6s + (size_t)slab_off1(si) * 20;
        const int cnt = nso1 * 20;
        for (int t = threadIdx.x; t < cnt; t += blockDim.x) {
            int m = t & 3, q = t >> 2;
            int tt = q % nso1, k = q / nso1;
            int so = si + 1 + tt, ci = 4 * k + m;
            d6[t] = W6[(size_t)so * HDIM + ci * NS + si];
        }
    }
}

__device__ __forceinline__ ull ffma2(ull a, ull b, ull c)
{
    ull d;
    asm("fma.rn.f32x2 %0, %1, %2, %3;" : "=l"(d) : "l"(a), "l"(b), "l"(c));
    return d;
}
__device__ __forceinline__ ull pack2(float lo, float hi)
{
    ull v;
    asm("mov.b64 %0, {%1, %2};" : "=l"(v) : "f"(lo), "f"(hi));
    return v;
}
__device__ __forceinline__ float hsum2(ull v)
{
    float lo, hi;
    asm("mov.b64 {%0, %1}, %2;" : "=f"(lo), "=f"(hi) : "l"(v));
    return lo + hi;
}
__device__ __forceinline__ float sigmoidf(float x) { return 1.0f / (1.0f + expf(-x)); }

#define BAR_DIAG() asm volatile("bar.sync 1, 160;" ::: "memory")

// load 5 weight float4 chunks for target j
#define WLOAD(W, j) do {                                                        \
    (W)[0] = *(const ulonglong2*)(wb + ((size_t)0 * nt + (j)) * 4);             \
    (W)[1] = *(const ulonglong2*)(wb + ((size_t)1 * nt + (j)) * 4);             \
    (W)[2] = *(const ulonglong2*)(wb + ((size_t)2 * nt + (j)) * 4);             \
    (W)[3] = *(const ulonglong2*)(wb + ((size_t)3 * nt + (j)) * 4);             \
    (W)[4] = *(const ulonglong2*)(wb + ((size_t)4 * nt + (j)) * 4);             \
} while (0)

// 20-MAC dual-row compute + dst RMW for target j with weights W[5]
#define WCOMP(W, j) do {                                                        \
    float* d0p = prl + r0 * PSTR + (j);                                         \
    float* d1p = prl + r1 * PSTR + (j);                                         \
    ull a0 = pack2(*d0p, 0.0f);                                                 \
    ull a1 = pack2(*d1p, 0.0f);                                                 \
    a0 = ffma2((W)[0].x, h0[0].x, a0); a1 = ffma2((W)[0].x, h1[0].x, a1);       \
    a0 = ffma2((W)[0].y, h0[0].y, a0); a1 = ffma2((W)[0].y, h1[0].y, a1);       \
    a0 = ffma2((W)[1].x, h0[1].x, a0); a1 = ffma2((W)[1].x, h1[1].x, a1);       \
    a0 = ffma2((W)[1].y, h0[1].y, a0); a1 = ffma2((W)[1].y, h1[1].y, a1);       \
    a0 = ffma2((W)[2].x, h0[2].x, a0); a1 = ffma2((W)[2].x, h1[2].x, a1);       \
    a0 = ffma2((W)[2].y, h0[2].y, a0); a1 = ffma2((W)[2].y, h1[2].y, a1);       \
    a0 = ffma2((W)[3].x, h0[3].x, a0); a1 = ffma2((W)[3].x, h1[3].x, a1);       \
    a0 = ffma2((W)[3].y, h0[3].y, a0); a1 = ffma2((W)[3].y, h1[3].y, a1);       \
    a0 = ffma2((W)[4].x, h0[4].x, a0); a1 = ffma2((W)[4].x, h1[4].x, a1);       \
    a0 = ffma2((W)[4].y, h0[4].y, a0); a1 = ffma2((W)[4].y, h1[4].y, a1);       \
    *d0p = hsum2(a0);                                                           \
    *d1p = hsum2(a1);                                                           \
} while (0)

__global__ void __launch_bounds__(T, 1)
net_kernel(const float* __restrict__ u, float* __restrict__ out)
{
    extern __shared__ float sm[];
    float* pre  = sm;                       // [5][8][PSTR]
    float* pre6 = pre + 5 * MROWS * PSTR;   // [8][P6STR]
    float* hbt  = pre6 + MROWS * P6STR;     // [5][8][20]
    float* usm  = hbt + 5 * 160;            // [8][64]
    float* wd   = usm + 512;                // [2020]
    float* sv   = wd + 2020;                // [8]

    const int tid = threadIdx.x;
    const int pair = tid & 3, jl = tid >> 2;     // jl in 0..127
    const int r0 = 2 * pair, r1 = r0 + 1;

    for (int k = tid; k < 5 * MROWS * PSTR; k += T) pre[k] = 0.0f;
    for (int k = tid; k < MROWS * P6STR; k += T) pre6[k] = 0.0f;
    {
        int ii = tid >> 3, rr = tid & 7;
        usm[rr * NS + ii] = u[(size_t)ii * BATCH + (size_t)blockIdx.x * MROWS + rr];
    }
    for (int k = tid; k < 2020; k += T) wd[k] = g_Wd[k];
    __syncthreads();

    for (int i = 0; i < NS; ++i) {
        // ===== diagonal chain: 160 threads =====
        if (tid < 160) {
            const int dr = tid / 20, dc = tid - (tid / 20) * 20;
            hbt[dr * 20 + dc] = sigmoidf(pre[dr * PSTR + i * HID + dc]);
            BAR_DIAG();
            #pragma unroll 1
            for (int lv = 0; lv < 4; ++lv) {
                float acc = pre[((lv + 1) * MROWS + dr) * PSTR + i * HID + dc];
                float acc2 = 0.0f;
                const float* w  = wd + lv * 400 + dc;
                const float* hh = hbt + lv * 160 + dr * 20;
                #pragma unroll
                for (int ci = 0; ci < 10; ++ci) {
                    acc  = fmaf(w[(2 * ci)     * 20], hh[2 * ci],     acc);
                    acc2 = fmaf(w[(2 * ci + 1) * 20], hh[2 * ci + 1], acc2);
                }
                hbt[(lv + 1) * 160 + dr * 20 + dc] = sigmoidf(acc + acc2);
                BAR_DIAG();
            }
            if (tid < MROWS) {                           // fc6 diag + sample
                float acc = pre6[tid * P6STR + i];
                const float* hh = hbt + 4 * 160 + tid * 20;
                #pragma unroll
                for (int ci = 0; ci < 20; ++ci) acc = fmaf(wd[2000 + ci], hh[ci], acc);
                float x = sigmoidf(acc);
                out[((size_t)blockIdx.x * MROWS + tid) * NS + i] = x;
                sv[tid] = (x >= usm[tid * NS + i]) ? 1.0f : -1.0f;
            }
        }
        __syncthreads();

        // ===== scatter phase =====
        if (i < 63) {
            const int nso1 = 63 - i;
            const int nt = nso1 * HID;
            const int tbase = (i + 1) * HID;
            const size_t soff = (size_t)slab_off1(i);

            // fc2..fc5, software-pipelined weight loads (2-deep ping-pong)
            #pragma unroll 1
            for (int l = 0; l < 4; ++l) {
                const float* wb = g_Ws4 + (size_t)l * LVL + soff * 400;
                float* prl = pre + (size_t)(l + 1) * MROWS * PSTR + tbase;
                ulonglong2 h0[5], h1[5];
                {
                    const ulonglong2* p0 = (const ulonglong2*)(hbt + l * 160 + r0 * 20);
                    const ulonglong2* p1 = (const ulonglong2*)(hbt + l * 160 + r1 * 20);
                    #pragma unroll
                    for (int q = 0; q < 5; ++q) { h0[q] = p0[q]; h1[q] = p1[q]; }
                }
                int j0 = jl;
                if (j0 < nt) {
                    ulonglong2 wA[5], wB[5];
                    WLOAD(wA, j0);
                    for (;;) {
                        int j1 = j0 + NJJ;
                        if (j1 >= nt) { WCOMP(wA, j0); break; }
                        WLOAD(wB, j1);
                        WCOMP(wA, j0);
                        j0 = j1 + NJJ;
                        if (j0 >= nt) { WCOMP(wB, j1); break; }
                        WLOAD(wA, j0);
                        WCOMP(wB, j1);
                    }
                }
            }
            // fc6 (single round)
            if (jl < nso1) {
                const float* wb6 = g_W6s + soff * 20;
                const ulonglong2* hp0 = (const ulonglong2*)(hbt + 4 * 160 + r0 * 20);
                const ulonglong2* hp1 = (const ulonglong2*)(hbt + 4 * 160 + r1 * 20);
                float* d0p = pre6 + r0 * P6STR + (i + 1 + jl);
                float* d1p = pre6 + r1 * P6STR + (i + 1 + jl);
                ull a0 = pack2(*d0p, 0.0f);
                ull a1 = pack2(*d1p, 0.0f);
                #pragma unroll
                for (int k = 0; k < 5; ++k) {
                    ulonglong2 wv = *(const ulonglong2*)(wb6 + ((size_t)k * nso1 + jl) * 4);
                    ulonglong2 h0v = hp0[k], h1v = hp1[k];
                    a0 = ffma2(wv.x, h0v.x, a0); a0 = ffma2(wv.y, h0v.y, a0);
                    a1 = ffma2(wv.x, h1v.x, a1); a1 = ffma2(wv.y, h1v.y, a1);
                }
                *d0p = hsum2(a0);
                *d1p = hsum2(a1);
            }
            // fc1 rank-1
            {
                const float* wb1 = g_W1s + soff * 20;
                float* p1 = pre + tbase;
                float s0 = sv[0], s1 = sv[1], s2 = sv[2], s3 = sv[3];
                float s4 = sv[4], s5 = sv[5], s6 = sv[6], s7 = sv[7];
                for (int j = tid; j < nt; j += T) {
                    float w = wb1[j];
                    p1[0 * PSTR + j] += w * s0;  p1[1 * PSTR + j] += w * s1;
                    p1[2 * PSTR + j] += w * s2;  p1[3 * PSTR + j] += w * s3;
                    p1[4 * PSTR + j] += w * s4;  p1[5 * PSTR + j] += w * s5;
                    p1[6 * PSTR + j] += w * s6;  p1[7 * PSTR + j] += w * s7;
                }
            }
            // prefetch next step's diag weights
            {
                const float* src = g_Wd + (size_t)(i + 1) * 2020;
                for (int k = tid; k < 2020; k += T) wd[k] = src[k];
            }
        }
        __syncthreads();
    }
}

extern "C" void kernel_launch(void* const* d_in, const int* in_sizes, int n_in,
                              void* d_out, int out_size)
{
    (void)in_sizes; (void)n_in; (void)out_size;
    const float* u  = (const float*)d_in[1];
    const float* W1 = (const float*)d_in[2];
    const float* W2 = (const float*)d_in[3];
    const float* W3 = (const float*)d_in[4];
    const float* W4 = (const float*)d_in[5];
    const float* W5 = (const float*)d_in[6];
    const float* W6 = (const float*)d_in[7];
    float* out = (float*)d_out;

    dim3 pg(64, 6);
    prep_scatter<<<pg, 256>>>(W1, W2, W3, W4, W5, W6);

    const int smem_bytes = (5 * MROWS * PSTR + MROWS * P6STR + 5 * 160
                            + 512 + 2020 + 8) * (int)sizeof(float);   // ~221 KB
    cudaFuncSetAttribute(net_kernel, cudaFuncAttributeMaxDynamicSharedMemorySize, smem_bytes);
    net_kernel<<<BATCH / MROWS, T, smem_bytes>>>(u, out);
}